// round 1
// baseline (speedup 1.0000x reference)
#include <cuda_runtime.h>
#include <float.h>

#define NB 32
#define NS 512
#define NH 1024
#define NCAND 256
#define NL 34
#define TPB1 128

// Scratch (no allocations allowed): pooled [NCAND, 2H] + sorted candidate lists.
__device__ float g_pooled[NCAND * 2 * NH];
__device__ int g_scut[NCAND];
__device__ int g_sidx[NCAND];
__device__ int g_off[NB + 1];

// ---------------------------------------------------------------------------
// Kernel 0: rank-sort candidates by (batch, cut, idx). O(N^2) with N=256,
// single block. Produces globally sorted (cut, idx) arrays grouped by batch,
// plus per-batch offsets.
// ---------------------------------------------------------------------------
__global__ void k_build(const int* __restrict__ cb, const int* __restrict__ cc) {
    __shared__ int sb[NCAND], sc[NCAND];
    int i = threadIdx.x;
    sb[i] = cb[i];
    sc[i] = cc[i];
    __syncthreads();
    int bi = sb[i], ci = sc[i];
    int rank = 0;
#pragma unroll 8
    for (int j = 0; j < NCAND; j++) {
        int bj = sb[j], cj = sc[j];
        bool less = (bj < bi) || (bj == bi && (cj < ci || (cj == ci && j < i)));
        rank += (int)less;
    }
    g_scut[rank] = ci;
    g_sidx[rank] = i;
    if (i <= NB) {
        int cnt = 0;
#pragma unroll 8
        for (int j = 0; j < NCAND; j++) cnt += (sb[j] < i);
        g_off[i] = cnt;
    }
}

// ---------------------------------------------------------------------------
// Kernel 1: per-batch forward prefix-max scan and backward suffix-max scan.
// Block = (batch b, h-tile). Thread owns one h. When the forward running max
// reaches position cut-1 we emit pooledL for every candidate of this batch
// with that cut (sorted list -> uniform pointer walk, no divergence).
// Backward pass emits pooledR at s == cut.
// Reads hidden exactly twice (128 MB total); second pass is L2-resident.
// ---------------------------------------------------------------------------
__global__ void k_pool(const float* __restrict__ hidden) {
    int b = blockIdx.y;
    int h = blockIdx.x * TPB1 + threadIdx.x;
    int start = g_off[b], end = g_off[b + 1];
    int cnt = end - start;
    if (cnt == 0) return;

    __shared__ int sc[NCAND];
    __shared__ int si[NCAND];
    for (int t = threadIdx.x; t < cnt; t += TPB1) {
        sc[t] = g_scut[start + t];
        si[t] = g_sidx[start + t];
    }
    __syncthreads();

    const float* base = hidden + ((size_t)b * NS) * NH + h;

    // Forward scan: pooledL[cand] = max over s < cut  (emit when s+1 == cut)
    float run = -FLT_MAX;
    int p = 0;
    for (int s0 = 0; s0 < NS; s0 += 8) {
        float v[8];
#pragma unroll
        for (int k = 0; k < 8; k++) v[k] = base[(size_t)(s0 + k) * NH];
#pragma unroll
        for (int k = 0; k < 8; k++) {
            run = fmaxf(run, v[k]);
            int s = s0 + k;
            while (p < cnt && sc[p] == s + 1) {
                g_pooled[(size_t)si[p] * (2 * NH) + h] = run;
                p++;
            }
        }
    }

    // Backward scan: pooledR[cand] = max over s >= cut (emit when s == cut)
    run = -FLT_MAX;
    p = cnt - 1;
    for (int s0 = NS - 8; s0 >= 0; s0 -= 8) {
        float v[8];
#pragma unroll
        for (int k = 0; k < 8; k++) v[k] = base[(size_t)(s0 + k) * NH];
#pragma unroll
        for (int k = 7; k >= 0; k--) {
            run = fmaxf(run, v[k]);
            int s = s0 + k;
            while (p >= 0 && sc[p] == s) {
                g_pooled[(size_t)si[p] * (2 * NH) + NH + h] = run;
                p--;
            }
        }
    }
}

// ---------------------------------------------------------------------------
// Kernel 2: logits[256, 34] = pooled[256, 2048] @ W[2048, 34] + b.
// 64 blocks x 256 threads. Block handles 4 candidates (keeps W L1/L2-hot,
// ~64x W reuse instead of 256x). Warp pair per candidate, each warp owns half
// of K. Lane l (0..16) accumulates labels 2l, 2l+1 via float2 W loads
// (row byte stride 136 -> every row 8B aligned). 4-way split accumulators
// break the FMA dependency chain. Final reduce + bias via smem.
// ---------------------------------------------------------------------------
__global__ void k_gemm(const float* __restrict__ W,
                       const float* __restrict__ bias,
                       float* __restrict__ out) {
    __shared__ float sp[8][NL];
    int tid = threadIdx.x;
    int wid = tid >> 5;
    int lane = tid & 31;
    int cand = blockIdx.x * 4 + (wid >> 1);
    int kbase = (wid & 1) * NH;  // 2H = 2048 split into two 1024 halves

    if (lane < 17) {
        const float* prow = g_pooled + (size_t)cand * (2 * NH) + kbase;
        const float* wbase = W + (size_t)kbase * NL + 2 * lane;
        float ax0 = 0.f, ay0 = 0.f, ax1 = 0.f, ay1 = 0.f;
        float ax2 = 0.f, ay2 = 0.f, ax3 = 0.f, ay3 = 0.f;
        for (int k = 0; k < NH; k += 4) {
            float a0 = prow[k + 0];
            float a1 = prow[k + 1];
            float a2 = prow[k + 2];
            float a3 = prow[k + 3];
            float2 w0 = *reinterpret_cast<const float2*>(wbase + (size_t)(k + 0) * NL);
            float2 w1 = *reinterpret_cast<const float2*>(wbase + (size_t)(k + 1) * NL);
            float2 w2 = *reinterpret_cast<const float2*>(wbase + (size_t)(k + 2) * NL);
            float2 w3 = *reinterpret_cast<const float2*>(wbase + (size_t)(k + 3) * NL);
            ax0 += a0 * w0.x; ay0 += a0 * w0.y;
            ax1 += a1 * w1.x; ay1 += a1 * w1.y;
            ax2 += a2 * w2.x; ay2 += a2 * w2.y;
            ax3 += a3 * w3.x; ay3 += a3 * w3.y;
        }
        int l2 = lane * 2;
        sp[wid][l2] = (ax0 + ax1) + (ax2 + ax3);
        sp[wid][l2 + 1] = (ay0 + ay1) + (ay2 + ay3);
    }
    __syncthreads();
    if (tid < 4 * NL) {
        int c = tid / NL;
        int l = tid - c * NL;
        out[(size_t)(blockIdx.x * 4 + c) * NL + l] =
            sp[c * 2][l] + sp[c * 2 + 1][l] + bias[l];
    }
}

// ---------------------------------------------------------------------------
extern "C" void kernel_launch(void* const* d_in, const int* in_sizes, int n_in,
                              void* d_out, int out_size) {
    const float* hidden = (const float*)d_in[0];
    const float* W = (const float*)d_in[1];
    const float* bias = (const float*)d_in[2];
    const int* cb = (const int*)d_in[3];
    const int* cc = (const int*)d_in[4];
    float* out = (float*)d_out;

    k_build<<<1, NCAND>>>(cb, cc);
    dim3 g1(NH / TPB1, NB);
    k_pool<<<g1, TPB1>>>(hidden);
    k_gemm<<<NCAND / 4, 256>>>(W, bias, out);
}

// round 2
// speedup vs baseline: 2.0779x; 2.0779x over previous
#include <cuda_runtime.h>
#include <float.h>

#define NB 32
#define NS 512
#define NH 1024
#define NCAND 256
#define NL 34
#define NCH 16      // chunks per sequence
#define CSZ 32      // tokens per chunk

// Scratch (__device__ globals; no allocation allowed)
__device__ float g_cmax[NB * NCH * NH];          // 2 MB  chunk maxes
__device__ float g_pref[NB * (NCH + 1) * NH];    // 2.2 MB pref[q] = max chunks < q
__device__ float g_suf[NB * (NCH + 1) * NH];     // 2.2 MB suf[q]  = max chunks >= q
__device__ float g_pooled[NCAND * 2 * NH];       // 2 MB

// ---------------------------------------------------------------------------
// Phase A: chunkmax[b,q,h] = max over 32 tokens. 16384 blocks-worth of
// parallelism (grid 4x16x32, 256 thr), 32-deep load batch per thread for MLP.
// Reads hidden exactly once (64 MB) -> DRAM-roofline bound.
// ---------------------------------------------------------------------------
__global__ void k_chunkmax(const float* __restrict__ hidden) {
    int h = blockIdx.x * 256 + threadIdx.x;
    int q = blockIdx.y;
    int b = blockIdx.z;
    const float* base = hidden + ((size_t)(b * NS + q * CSZ)) * NH + h;
    float v[CSZ];
#pragma unroll
    for (int k = 0; k < CSZ; k++) v[k] = base[(size_t)k * NH];
    float m = -FLT_MAX;
#pragma unroll
    for (int k = 0; k < CSZ; k++) m = fmaxf(m, v[k]);
    g_cmax[((size_t)b * NCH + q) * NH + h] = m;
}

// ---------------------------------------------------------------------------
// Phase B: prefix/suffix max over the 16 chunk values (all in registers).
// pref[q] = max of chunks < q (pref[0] = -inf); suf[q] = max of chunks >= q
// (suf[16] = -inf). Tiny kernel, L2-resident.
// ---------------------------------------------------------------------------
__global__ void k_scan() {
    int h = blockIdx.x * 256 + threadIdx.x;
    int b = blockIdx.y;
    const float* cm = g_cmax + (size_t)b * NCH * NH + h;
    float v[NCH];
#pragma unroll
    for (int q = 0; q < NCH; q++) v[q] = cm[(size_t)q * NH];

    float* pf = g_pref + (size_t)b * (NCH + 1) * NH + h;
    float run = -FLT_MAX;
#pragma unroll
    for (int q = 0; q < NCH; q++) {
        pf[(size_t)q * NH] = run;
        run = fmaxf(run, v[q]);
    }
    pf[(size_t)NCH * NH] = run;

    float* sf = g_suf + (size_t)b * (NCH + 1) * NH + h;
    run = -FLT_MAX;
    sf[(size_t)NCH * NH] = run;
#pragma unroll
    for (int q = NCH - 1; q >= 0; q--) {
        run = fmaxf(run, v[q]);
        sf[(size_t)q * NH] = run;
    }
}

// ---------------------------------------------------------------------------
// Phase C: per-candidate pooled vectors. Candidate n with cut c, q = c/32,
// r = c%32:
//   pooledL = max(pref[b][q],   max of tokens [q*32, q*32+r) )
//   pooledR = max(suf[b][q+1],  max of tokens [q*32+r, q*32+32) )
// Each thread reads the 32 tokens of chunk q (L2-hot: 32 MB total from L2).
// Fully candidate-parallel: 2048 blocks x 128 thr.
// ---------------------------------------------------------------------------
__global__ void k_cand(const float* __restrict__ hidden,
                       const int* __restrict__ cb,
                       const int* __restrict__ cc) {
    int n = blockIdx.y;
    int h = blockIdx.x * 128 + threadIdx.x;
    int b = cb[n];
    int c = cc[n];
    int q = c >> 5;
    int r = c & 31;

    const float* base = hidden + ((size_t)(b * NS + q * CSZ)) * NH + h;
    float v[CSZ];
#pragma unroll
    for (int k = 0; k < CSZ; k++) v[k] = base[(size_t)k * NH];

    float ml = -FLT_MAX, mr = -FLT_MAX;
#pragma unroll
    for (int k = 0; k < CSZ; k++) {
        if (k < r) ml = fmaxf(ml, v[k]);
        else       mr = fmaxf(mr, v[k]);
    }
    float pl = fmaxf(ml, g_pref[((size_t)b * (NCH + 1) + q) * NH + h]);
    float pr = fmaxf(mr, g_suf[((size_t)b * (NCH + 1) + q + 1) * NH + h]);
    g_pooled[(size_t)n * (2 * NH) + h] = pl;
    g_pooled[(size_t)n * (2 * NH) + NH + h] = pr;
}

// ---------------------------------------------------------------------------
// Phase D: logits[256,34] = pooled[256,2048] @ W[2048,34] + b.
// Block = 4 candidates, warp pair per candidate (K split in halves), lane l
// (0..16) owns labels {2l, 2l+1} via float2 W loads; 4-way split accumulators.
// ---------------------------------------------------------------------------
__global__ void k_gemm(const float* __restrict__ W,
                       const float* __restrict__ bias,
                       float* __restrict__ out) {
    __shared__ float sp[8][NL];
    int tid = threadIdx.x;
    int wid = tid >> 5;
    int lane = tid & 31;
    int cand = blockIdx.x * 4 + (wid >> 1);
    int kbase = (wid & 1) * NH;

    if (lane < 17) {
        const float* prow = g_pooled + (size_t)cand * (2 * NH) + kbase;
        const float* wbase = W + (size_t)kbase * NL + 2 * lane;
        float ax0 = 0.f, ay0 = 0.f, ax1 = 0.f, ay1 = 0.f;
        float ax2 = 0.f, ay2 = 0.f, ax3 = 0.f, ay3 = 0.f;
        for (int k = 0; k < NH; k += 4) {
            float a0 = prow[k + 0];
            float a1 = prow[k + 1];
            float a2 = prow[k + 2];
            float a3 = prow[k + 3];
            float2 w0 = *reinterpret_cast<const float2*>(wbase + (size_t)(k + 0) * NL);
            float2 w1 = *reinterpret_cast<const float2*>(wbase + (size_t)(k + 1) * NL);
            float2 w2 = *reinterpret_cast<const float2*>(wbase + (size_t)(k + 2) * NL);
            float2 w3 = *reinterpret_cast<const float2*>(wbase + (size_t)(k + 3) * NL);
            ax0 += a0 * w0.x; ay0 += a0 * w0.y;
            ax1 += a1 * w1.x; ay1 += a1 * w1.y;
            ax2 += a2 * w2.x; ay2 += a2 * w2.y;
            ax3 += a3 * w3.x; ay3 += a3 * w3.y;
        }
        int l2 = lane * 2;
        sp[wid][l2]     = (ax0 + ax1) + (ax2 + ax3);
        sp[wid][l2 + 1] = (ay0 + ay1) + (ay2 + ay3);
    }
    __syncthreads();
    if (tid < 4 * NL) {
        int c = tid / NL;
        int l = tid - c * NL;
        out[(size_t)(blockIdx.x * 4 + c) * NL + l] =
            sp[c * 2][l] + sp[c * 2 + 1][l] + bias[l];
    }
}

// ---------------------------------------------------------------------------
extern "C" void kernel_launch(void* const* d_in, const int* in_sizes, int n_in,
                              void* d_out, int out_size) {
    const float* hidden = (const float*)d_in[0];
    const float* W = (const float*)d_in[1];
    const float* bias = (const float*)d_in[2];
    const int* cb = (const int*)d_in[3];
    const int* cc = (const int*)d_in[4];
    float* out = (float*)d_out;

    dim3 gA(NH / 256, NCH, NB);
    k_chunkmax<<<gA, 256>>>(hidden);

    dim3 gB(NH / 256, NB);
    k_scan<<<gB, 256>>>();

    dim3 gC(NH / 128, NCAND);
    k_cand<<<gC, 128>>>(hidden, cb, cc);

    k_gemm<<<NCAND / 4, 256>>>(W, bias, out);
}

// round 3
// speedup vs baseline: 4.6754x; 2.2500x over previous
#include <cuda_runtime.h>
#include <float.h>

#define NB 32
#define NS 512
#define NH 1024
#define NCAND 256
#define NL 34
#define NCH 16      // chunks per sequence
#define CSZ 32      // tokens per chunk

// Scratch (__device__ globals; no allocation allowed)
__device__ float g_cmax[NB * NCH * NH];          // chunk maxes
__device__ float g_pref[NB * (NCH + 1) * NH];    // pref[q] = max chunks < q
__device__ float g_suf[NB * (NCH + 1) * NH];     // suf[q]  = max chunks >= q
__device__ float g_pooled[NCAND * 2 * NH];

// ---------------------------------------------------------------------------
// Phase A: chunkmax[b,q,h] = max over 32 tokens. Reads hidden once (64 MB),
// 32-deep load batch per thread -> DRAM-roofline bound.
// ---------------------------------------------------------------------------
__global__ void k_chunkmax(const float* __restrict__ hidden) {
    int h = blockIdx.x * 256 + threadIdx.x;
    int q = blockIdx.y;
    int b = blockIdx.z;
    const float* base = hidden + ((size_t)(b * NS + q * CSZ)) * NH + h;
    float v[CSZ];
#pragma unroll
    for (int k = 0; k < CSZ; k++) v[k] = base[(size_t)k * NH];
    float m = -FLT_MAX;
#pragma unroll
    for (int k = 0; k < CSZ; k++) m = fmaxf(m, v[k]);
    g_cmax[((size_t)b * NCH + q) * NH + h] = m;
}

// ---------------------------------------------------------------------------
// Phase B: prefix/suffix max over the 16 chunk values (registers only).
// ---------------------------------------------------------------------------
__global__ void k_scan() {
    int h = blockIdx.x * 256 + threadIdx.x;
    int b = blockIdx.y;
    const float* cm = g_cmax + (size_t)b * NCH * NH + h;
    float v[NCH];
#pragma unroll
    for (int q = 0; q < NCH; q++) v[q] = cm[(size_t)q * NH];

    float* pf = g_pref + (size_t)b * (NCH + 1) * NH + h;
    float run = -FLT_MAX;
#pragma unroll
    for (int q = 0; q < NCH; q++) {
        pf[(size_t)q * NH] = run;
        run = fmaxf(run, v[q]);
    }
    pf[(size_t)NCH * NH] = run;

    float* sf = g_suf + (size_t)b * (NCH + 1) * NH + h;
    run = -FLT_MAX;
    sf[(size_t)NCH * NH] = run;
#pragma unroll
    for (int q = NCH - 1; q >= 0; q--) {
        run = fmaxf(run, v[q]);
        sf[(size_t)q * NH] = run;
    }
}

// ---------------------------------------------------------------------------
// Phase C: per-candidate pooled vectors. Candidate n, cut c, q=c/32, r=c%32:
//   pooledL = max(pref[b][q],  tokens [q*32, q*32+r))
//   pooledR = max(suf[b][q+1], tokens [q*32+r, q*32+32))
// Chunk reads are L2-hot (32 MB total from L2).
// ---------------------------------------------------------------------------
__global__ void k_cand(const float* __restrict__ hidden,
                       const int* __restrict__ cb,
                       const int* __restrict__ cc) {
    int n = blockIdx.y;
    int h = blockIdx.x * 128 + threadIdx.x;
    int b = cb[n];
    int c = cc[n];
    int q = c >> 5;
    int r = c & 31;

    const float* base = hidden + ((size_t)(b * NS + q * CSZ)) * NH + h;
    float v[CSZ];
#pragma unroll
    for (int k = 0; k < CSZ; k++) v[k] = base[(size_t)k * NH];

    float ml = -FLT_MAX, mr = -FLT_MAX;
#pragma unroll
    for (int k = 0; k < CSZ; k++) {
        if (k < r) ml = fmaxf(ml, v[k]);
        else       mr = fmaxf(mr, v[k]);
    }
    float pl = fmaxf(ml, g_pref[((size_t)b * (NCH + 1) + q) * NH + h]);
    float pr = fmaxf(mr, g_suf[((size_t)b * (NCH + 1) + q + 1) * NH + h]);
    g_pooled[(size_t)n * (2 * NH) + h] = pl;
    g_pooled[(size_t)n * (2 * NH) + NH + h] = pr;
}

// ---------------------------------------------------------------------------
// Phase D: logits[256,34] = pooled[256,2048] @ W[2048,34] + bias.
// Block = 1 candidate, 8 warps; warp w owns K-slice [w*256, w*256+256).
// Lane l (0..16) accumulates labels {2l, 2l+1} via float2 W loads; 4-way
// split accumulators. 256 blocks x 8 warps = 2048 warps (~3.5/SMSP) so load
// latency is covered (round-2 version had 512 warps -> issue=4.3%).
// ---------------------------------------------------------------------------
__global__ void k_gemm(const float* __restrict__ W,
                       const float* __restrict__ bias,
                       float* __restrict__ out) {
    __shared__ float sp[8][NL];
    int tid = threadIdx.x;
    int wid = tid >> 5;
    int lane = tid & 31;
    int cand = blockIdx.x;
    int kbase = wid * 256;  // 2048 / 8 warps

    if (lane < 17) {
        const float* prow = g_pooled + (size_t)cand * (2 * NH) + kbase;
        const float* wbase = W + (size_t)kbase * NL + 2 * lane;
        float ax0 = 0.f, ay0 = 0.f, ax1 = 0.f, ay1 = 0.f;
        float ax2 = 0.f, ay2 = 0.f, ax3 = 0.f, ay3 = 0.f;
#pragma unroll 4
        for (int k = 0; k < 256; k += 4) {
            float a0 = prow[k + 0];
            float a1 = prow[k + 1];
            float a2 = prow[k + 2];
            float a3 = prow[k + 3];
            float2 w0 = *reinterpret_cast<const float2*>(wbase + (size_t)(k + 0) * NL);
            float2 w1 = *reinterpret_cast<const float2*>(wbase + (size_t)(k + 1) * NL);
            float2 w2 = *reinterpret_cast<const float2*>(wbase + (size_t)(k + 2) * NL);
            float2 w3 = *reinterpret_cast<const float2*>(wbase + (size_t)(k + 3) * NL);
            ax0 += a0 * w0.x; ay0 += a0 * w0.y;
            ax1 += a1 * w1.x; ay1 += a1 * w1.y;
            ax2 += a2 * w2.x; ay2 += a2 * w2.y;
            ax3 += a3 * w3.x; ay3 += a3 * w3.y;
        }
        int l2 = lane * 2;
        sp[wid][l2]     = (ax0 + ax1) + (ax2 + ax3);
        sp[wid][l2 + 1] = (ay0 + ay1) + (ay2 + ay3);
    }
    __syncthreads();
    if (tid < NL) {
        float s = bias[tid];
#pragma unroll
        for (int w = 0; w < 8; w++) s += sp[w][tid];
        out[(size_t)cand * NL + tid] = s;
    }
}

// ---------------------------------------------------------------------------
extern "C" void kernel_launch(void* const* d_in, const int* in_sizes, int n_in,
                              void* d_out, int out_size) {
    const float* hidden = (const float*)d_in[0];
    const float* W = (const float*)d_in[1];
    const float* bias = (const float*)d_in[2];
    const int* cb = (const int*)d_in[3];
    const int* cc = (const int*)d_in[4];
    float* out = (float*)d_out;

    dim3 gA(NH / 256, NCH, NB);
    k_chunkmax<<<gA, 256>>>(hidden);

    dim3 gB(NH / 256, NB);
    k_scan<<<gB, 256>>>();

    dim3 gC(NH / 128, NCAND);
    k_cand<<<gC, 128>>>(hidden, cb, cc);

    k_gemm<<<NCAND, 256>>>(W, bias, out);
}

// round 4
// speedup vs baseline: 5.7895x; 1.2383x over previous
#include <cuda_runtime.h>
#include <float.h>

#define NB 32
#define NS 512
#define NH 1024
#define NCAND 256
#define NL 34
#define NCH 16      // chunks per sequence
#define CSZ 32      // tokens per chunk
#define SPLIT 4     // K-split for gemm
#define CPB 4       // candidates per gemm block
#define KS (2 * NH / SPLIT)   // 512

// Scratch (__device__ globals; no allocation allowed)
__device__ float g_cmax[NB * NCH * NH];
__device__ float g_pref[NB * (NCH + 1) * NH];
__device__ float g_suf[NB * (NCH + 1) * NH];
__device__ float g_pooled[NCAND * 2 * NH];
__device__ float g_Wt[NL * 2 * NH];             // W transposed [34][2048]
__device__ float g_part[SPLIT * NCAND * NL];    // gemm partials

// ---------------------------------------------------------------------------
// Phase A: chunkmax[b,q,h] = max over 32 tokens. Reads hidden once (64 MB).
// ---------------------------------------------------------------------------
__global__ void k_chunkmax(const float* __restrict__ hidden) {
    int h = blockIdx.x * 256 + threadIdx.x;
    int q = blockIdx.y;
    int b = blockIdx.z;
    const float* base = hidden + ((size_t)(b * NS + q * CSZ)) * NH + h;
    float v[CSZ];
#pragma unroll
    for (int k = 0; k < CSZ; k++) v[k] = base[(size_t)k * NH];
    float m = -FLT_MAX;
#pragma unroll
    for (int k = 0; k < CSZ; k++) m = fmaxf(m, v[k]);
    g_cmax[((size_t)b * NCH + q) * NH + h] = m;
}

// ---------------------------------------------------------------------------
// Phase B: prefix/suffix max over the 16 chunk values (registers only).
// ---------------------------------------------------------------------------
__global__ void k_scan() {
    int h = blockIdx.x * 256 + threadIdx.x;
    int b = blockIdx.y;
    const float* cm = g_cmax + (size_t)b * NCH * NH + h;
    float v[NCH];
#pragma unroll
    for (int q = 0; q < NCH; q++) v[q] = cm[(size_t)q * NH];

    float* pf = g_pref + (size_t)b * (NCH + 1) * NH + h;
    float run = -FLT_MAX;
#pragma unroll
    for (int q = 0; q < NCH; q++) {
        pf[(size_t)q * NH] = run;
        run = fmaxf(run, v[q]);
    }
    pf[(size_t)NCH * NH] = run;

    float* sf = g_suf + (size_t)b * (NCH + 1) * NH + h;
    run = -FLT_MAX;
    sf[(size_t)NCH * NH] = run;
#pragma unroll
    for (int q = NCH - 1; q >= 0; q--) {
        run = fmaxf(run, v[q]);
        sf[(size_t)q * NH] = run;
    }
}

// ---------------------------------------------------------------------------
// Phase C: per-candidate pooled vectors (chunk reads are L2-hot).
// ---------------------------------------------------------------------------
__global__ void k_cand(const float* __restrict__ hidden,
                       const int* __restrict__ cb,
                       const int* __restrict__ cc) {
    int n = blockIdx.y;
    int h = blockIdx.x * 128 + threadIdx.x;
    int b = cb[n];
    int c = cc[n];
    int q = c >> 5;
    int r = c & 31;

    const float* base = hidden + ((size_t)(b * NS + q * CSZ)) * NH + h;
    float v[CSZ];
#pragma unroll
    for (int k = 0; k < CSZ; k++) v[k] = base[(size_t)k * NH];

    float ml = -FLT_MAX, mr = -FLT_MAX;
#pragma unroll
    for (int k = 0; k < CSZ; k++) {
        if (k < r) ml = fmaxf(ml, v[k]);
        else       mr = fmaxf(mr, v[k]);
    }
    float pl = fmaxf(ml, g_pref[((size_t)b * (NCH + 1) + q) * NH + h]);
    float pr = fmaxf(mr, g_suf[((size_t)b * (NCH + 1) + q + 1) * NH + h]);
    g_pooled[(size_t)n * (2 * NH) + h] = pl;
    g_pooled[(size_t)n * (2 * NH) + NH + h] = pr;
}

// ---------------------------------------------------------------------------
// Phase D0: transpose W [2048,34] -> Wt [34,2048] so gemm loads coalesce.
// ---------------------------------------------------------------------------
__global__ void k_wt(const float* __restrict__ W) {
    int idx = blockIdx.x * 1024 + threadIdx.x;
    if (idx < NL * 2 * NH) {
        int l = idx >> 11;        // / 2048
        int k = idx & (2 * NH - 1);
        g_Wt[idx] = W[(size_t)k * NL + l];
    }
}

// ---------------------------------------------------------------------------
// Phase D1: warp-per-(cand,label) dot with K split in 4 quarters.
// Grid (64, 4) x 512 thr = 4096 warps. All 32 lanes live; both operands
// loaded as coalesced float4 (4 independent pairs per lane -> deep MLP).
// Block working set: 4 pooled rows (8 KB) + W quarter (70 KB) -> L1-hot.
// ---------------------------------------------------------------------------
__global__ void k_gemm() {
    int wid = threadIdx.x >> 5;
    int lane = threadIdx.x & 31;
    int kbase = blockIdx.y * KS;

#pragma unroll 1
    for (int d = wid; d < CPB * NL; d += 16) {
        int c = d / NL;
        int l = d - c * NL;
        int cand = blockIdx.x * CPB + c;
        const float4* a = (const float4*)(g_pooled + (size_t)cand * (2 * NH) + kbase);
        const float4* w = (const float4*)(g_Wt + (size_t)l * (2 * NH) + kbase);
        float s0 = 0.f, s1 = 0.f, s2 = 0.f, s3 = 0.f;
#pragma unroll
        for (int i = 0; i < KS / 128; i++) {   // 4 float4 pairs per lane
            float4 av = a[lane + i * 32];
            float4 wv = w[lane + i * 32];
            s0 += av.x * wv.x;
            s1 += av.y * wv.y;
            s2 += av.z * wv.z;
            s3 += av.w * wv.w;
        }
        float s = (s0 + s1) + (s2 + s3);
#pragma unroll
        for (int o = 16; o; o >>= 1) s += __shfl_xor_sync(0xffffffffu, s, o);
        if (lane == 0)
            g_part[((size_t)blockIdx.y * NCAND + cand) * NL + l] = s;
    }
}

// ---------------------------------------------------------------------------
// Phase D2: sum the 4 K-partials + bias (deterministic).
// ---------------------------------------------------------------------------
__global__ void k_red(const float* __restrict__ bias, float* __restrict__ out) {
    int i = blockIdx.x * 256 + threadIdx.x;
    if (i < NCAND * NL) {
        int l = i % NL;
        float s = bias[l];
#pragma unroll
        for (int p = 0; p < SPLIT; p++) s += g_part[p * NCAND * NL + i];
        out[i] = s;
    }
}

// ---------------------------------------------------------------------------
extern "C" void kernel_launch(void* const* d_in, const int* in_sizes, int n_in,
                              void* d_out, int out_size) {
    const float* hidden = (const float*)d_in[0];
    const float* W = (const float*)d_in[1];
    const float* bias = (const float*)d_in[2];
    const int* cb = (const int*)d_in[3];
    const int* cc = (const int*)d_in[4];
    float* out = (float*)d_out;

    k_wt<<<(NL * 2 * NH + 1023) / 1024, 1024>>>(W);

    dim3 gA(NH / 256, NCH, NB);
    k_chunkmax<<<gA, 256>>>(hidden);

    dim3 gB(NH / 256, NB);
    k_scan<<<gB, 256>>>();

    dim3 gC(NH / 128, NCAND);
    k_cand<<<gC, 128>>>(hidden, cb, cc);

    dim3 gD(NCAND / CPB, SPLIT);
    k_gemm<<<gD, 512>>>();

    k_red<<<(NCAND * NL + 255) / 256, 256>>>(bias, out);
}